// round 16
// baseline (speedup 1.0000x reference)
#include <cuda_runtime.h>
#include <cstdint>

// UnalignmentLoss: min over 17x17 shifts (step 2) of mean L1 between shifted
// x crop and fixed y center crop. x,y: (4,3,256,256) fp32, crop 224x224.
//
// R15 structure (empirical best) + 2-row software pipeline: one warp per
// (plane, shift-row i, 8-row chunk); rows processed in even/odd pairs with
// compile-time buffer offsets and pointer-increment addressing. x staged to
// swizzled smem (conflict-free STS.128 / one 10-granule LDS.v2.b64 batch);
// y prefetched as pre-packed f32x2 pairs. Packed f32x2 fma/add, abs = 64-bit
// AND. Separate 1-warp final kernel does the 289-way min.

#define NS    17
#define W_    256
#define TOLC  16
#define COUNT_F 602112.0f   // 4*3*224*224

__device__ float g_acc[NS * NS];   // zero at load; final_kernel restores 0

// ---- packed f32x2 helpers (uint64_t = b64 carrier) ----
__device__ __forceinline__ uint64_t f2add(uint64_t a, uint64_t b) {
    uint64_t r; asm("add.rn.f32x2 %0, %1, %2;" : "=l"(r) : "l"(a), "l"(b)); return r;
}
__device__ __forceinline__ uint64_t f2fma(uint64_t a, uint64_t b, uint64_t c) {
    uint64_t r; asm("fma.rn.f32x2 %0, %1, %2, %3;" : "=l"(r) : "l"(a), "l"(b), "l"(c)); return r;
}
__device__ __forceinline__ uint64_t f2abs(uint64_t a) {
    return a & 0x7FFFFFFF7FFFFFFFULL;
}
__device__ __forceinline__ void unpack2(uint64_t v, float& lo, float& hi) {
    asm("mov.b64 {%0, %1}, %2;" : "=f"(lo), "=f"(hi) : "l"(v));
}
__device__ __forceinline__ void sts128(unsigned addr, float4 v) {
    asm volatile("st.shared.v4.f32 [%0], {%1,%2,%3,%4};"
                 :: "r"(addr), "f"(v.x), "f"(v.y), "f"(v.z), "f"(v.w));
}
__device__ __forceinline__ void lds_2b64(unsigned addr, uint64_t& a, uint64_t& b) {
    asm volatile("ld.shared.v2.b64 {%0,%1}, [%2];" : "=l"(a), "=l"(b) : "r"(addr));
}
// XOR swizzle on 16B granule index (row = 64 granules): conflict-free for the
// 2-granule staging stores and the 10-granule strided window reads.
__device__ __forceinline__ int swz(int t) { return t ^ ((t >> 3) & 7); }

#define NEG1_X2 0xBF800000BF800000ULL   // packed (-1.0f, -1.0f)
#define BUF1    ((unsigned)(W_ * 4))    // byte offset of second smem buffer

__global__ __launch_bounds__(128) void corr_kernel(const float* __restrict__ x,
                                                   const float* __restrict__ y) {
    const int warp = threadIdx.x >> 5;
    const int lane = threadIdx.x & 31;
    const int bc   = blockIdx.z;       // plane
    const int i    = blockIdx.y;       // shift-row index (shift = 2*i)
    const int r0   = blockIdx.x * 32 + warp * 8;

    const float* xb = x + (size_t)bc * (W_ * W_);
    const float* yb = y + (size_t)bc * (W_ * W_);

    __shared__ __align__(16) float xs[4][2][W_];   // [warp][double-buffer][256]

    const unsigned base = (unsigned)__cvta_generic_to_shared(&xs[warp][0][0]);

    const int Lc = lane < 28 ? lane : 27;          // idle lanes: broadcast reads
    unsigned roff[10];
#pragma unroll
    for (int m = 0; m < 10; m++) roff[m] = (unsigned)(swz(2 * Lc + m) * 16);
    const unsigned s0 = (unsigned)(swz(2 * lane)     * 16);
    const unsigned s1 = (unsigned)(swz(2 * lane + 1) * 16);

    uint64_t acc[NS];
#pragma unroll
    for (int j = 0; j < NS; j++) acc[j] = 0ull;    // +0.0f,+0.0f

    // Row pointers (both strides: 64 16B-elements per image row).
    const float4*     xp = (const float4*)(xb + (size_t)(2 * i + r0) * W_);
    const ulonglong2* yp = (const ulonglong2*)(yb + (size_t)(TOLC + r0) * W_ + TOLC);

    // Prefetch row 0.
    float4     xa0 = xp[2 * lane], xc0 = xp[2 * lane + 1];
    ulonglong2 yA0 = yp[2 * lane], yB0 = yp[2 * lane + 1];

#define COMPUTE(boff, pyA, pyB)                                              \
    do {                                                                     \
        uint64_t wd[20];                                                     \
        _Pragma("unroll")                                                    \
        for (int m = 0; m < 10; m++)                                         \
            lds_2b64(base + (boff) + roff[m], wd[2 * m], wd[2 * m + 1]);     \
        _Pragma("unroll")                                                    \
        for (int j = 0; j < NS; j++) {                                       \
            uint64_t a0 = f2abs(f2fma((pyA).x, NEG1_X2, wd[j + 0]));         \
            uint64_t a1 = f2abs(f2fma((pyA).y, NEG1_X2, wd[j + 1]));         \
            uint64_t a2 = f2abs(f2fma((pyB).x, NEG1_X2, wd[j + 2]));         \
            uint64_t a3 = f2abs(f2fma((pyB).y, NEG1_X2, wd[j + 3]));         \
            acc[j] = f2add(acc[j], f2add(f2add(a0, a1), f2add(a2, a3)));     \
        }                                                                    \
    } while (0)

#pragma unroll 1
    for (int k = 0; k < 4; k++) {
        // ---- even row 2k -> buffer 0 ----
        sts128(base + s0, xa0);
        sts128(base + s1, xc0);
        const ulonglong2 y0A = yA0, y0B = yB0;

        // prefetch odd row 2k+1 (always exists)
        xp += 64; yp += 64;
        float4     xa1 = xp[2 * lane], xc1 = xp[2 * lane + 1];
        ulonglong2 yA1 = yp[2 * lane], yB1 = yp[2 * lane + 1];

        __syncwarp();
        COMPUTE(0u, y0A, y0B);

        // ---- odd row 2k+1 -> buffer 1 ----
        sts128(base + BUF1 + s0, xa1);
        sts128(base + BUF1 + s1, xc1);

        if (k < 3) {   // prefetch even row 2k+2
            xp += 64; yp += 64;
            xa0 = xp[2 * lane]; xc0 = xp[2 * lane + 1];
            yA0 = yp[2 * lane]; yB0 = yp[2 * lane + 1];
        }

        __syncwarp();
        COMPUTE(BUF1, yA1, yB1);
    }
#undef COMPUTE

    // Reduce: lane j keeps shift-column j's warp sum; idle lanes contribute 0.
    float keep = 0.0f;
#pragma unroll
    for (int j = 0; j < NS; j++) {
        float lo, hi; unpack2(acc[j], lo, hi);
        float v = (lane < 28) ? (lo + hi) : 0.0f;
#pragma unroll
        for (int off = 16; off; off >>= 1) v += __shfl_xor_sync(0xffffffffu, v, off);
        if (lane == j) keep = v;
    }
    if (lane < NS) atomicAdd(&g_acc[i * NS + lane], keep);
}

__global__ void final_kernel(float* __restrict__ out) {
    const int lane = threadIdx.x;
    float v = 3.4e38f;
    for (int idx = lane; idx < NS * NS; idx += 32) v = fminf(v, g_acc[idx]);
    __syncwarp();
    for (int idx = lane; idx < NS * NS; idx += 32) g_acc[idx] = 0.0f;  // reset
#pragma unroll
    for (int off = 16; off; off >>= 1)
        v = fminf(v, __shfl_xor_sync(0xffffffffu, v, off));
    if (lane == 0) out[0] = v * (1.0f / COUNT_F);
}

extern "C" void kernel_launch(void* const* d_in, const int* in_sizes, int n_in,
                              void* d_out, int out_size) {
    (void)in_sizes; (void)n_in; (void)out_size;
    const float* x = (const float*)d_in[0];
    const float* y = (const float*)d_in[1];
    float* out = (float*)d_out;

    dim3 grid(7, NS, 12);
    corr_kernel<<<grid, 128>>>(x, y);
    final_kernel<<<1, 32>>>(out);
}

// round 17
// speedup vs baseline: 1.0657x; 1.0657x over previous
#include <cuda_runtime.h>
#include <cstdint>

// UnalignmentLoss: min over 17x17 shifts (step 2) of mean L1 between shifted
// x crop and fixed y center crop. x,y: (4,3,256,256) fp32, crop 224x224.
//
// corr_kernel: R15 structure (empirical best) — one warp per (plane,
// shift-row i, 8-row chunk); x staged to swizzled smem (conflict-free
// STS.128 / one 10-granule LDS.v2.b64 batch); y prefetched as pre-packed
// f32x2 pairs. Packed f32x2 fma/add, abs = 64-bit AND.
// final_kernel: batched predicated loads (full MLP) + register tree-min.

#define NS    17
#define W_    256
#define TOLC  16
#define COUNT_F 602112.0f   // 4*3*224*224

__device__ float g_acc[NS * NS];   // zero at load; final_kernel restores 0

// ---- packed f32x2 helpers (uint64_t = b64 carrier) ----
__device__ __forceinline__ uint64_t f2add(uint64_t a, uint64_t b) {
    uint64_t r; asm("add.rn.f32x2 %0, %1, %2;" : "=l"(r) : "l"(a), "l"(b)); return r;
}
__device__ __forceinline__ uint64_t f2fma(uint64_t a, uint64_t b, uint64_t c) {
    uint64_t r; asm("fma.rn.f32x2 %0, %1, %2, %3;" : "=l"(r) : "l"(a), "l"(b), "l"(c)); return r;
}
__device__ __forceinline__ uint64_t f2abs(uint64_t a) {
    return a & 0x7FFFFFFF7FFFFFFFULL;
}
__device__ __forceinline__ void unpack2(uint64_t v, float& lo, float& hi) {
    asm("mov.b64 {%0, %1}, %2;" : "=f"(lo), "=f"(hi) : "l"(v));
}
__device__ __forceinline__ void sts128(unsigned addr, float4 v) {
    asm volatile("st.shared.v4.f32 [%0], {%1,%2,%3,%4};"
                 :: "r"(addr), "f"(v.x), "f"(v.y), "f"(v.z), "f"(v.w));
}
__device__ __forceinline__ void lds_2b64(unsigned addr, uint64_t& a, uint64_t& b) {
    asm volatile("ld.shared.v2.b64 {%0,%1}, [%2];" : "=l"(a), "=l"(b) : "r"(addr));
}
// XOR swizzle on 16B granule index (row = 64 granules): conflict-free for the
// 2-granule staging stores and the 10-granule strided window reads.
__device__ __forceinline__ int swz(int t) { return t ^ ((t >> 3) & 7); }

#define NEG1_X2 0xBF800000BF800000ULL   // packed (-1.0f, -1.0f)

__global__ __launch_bounds__(128) void corr_kernel(const float* __restrict__ x,
                                                   const float* __restrict__ y) {
    const int warp = threadIdx.x >> 5;
    const int lane = threadIdx.x & 31;
    const int bc   = blockIdx.z;       // plane
    const int i    = blockIdx.y;       // shift-row index (shift = 2*i)
    const int r0   = blockIdx.x * 32 + warp * 8;

    const float* xb = x + (size_t)bc * (W_ * W_);
    const float* yb = y + (size_t)bc * (W_ * W_);

    __shared__ __align__(16) float xs[4][2][W_];   // [warp][double-buffer][256]

    const unsigned base = (unsigned)__cvta_generic_to_shared(&xs[warp][0][0]);

    const int Lc = lane < 28 ? lane : 27;          // idle lanes: broadcast reads
    unsigned roff[10];
#pragma unroll
    for (int m = 0; m < 10; m++) roff[m] = (unsigned)(swz(2 * Lc + m) * 16);
    const unsigned s0 = (unsigned)(swz(2 * lane)     * 16);
    const unsigned s1 = (unsigned)(swz(2 * lane + 1) * 16);

    uint64_t acc[NS];
#pragma unroll
    for (int j = 0; j < NS; j++) acc[j] = 0ull;    // +0.0f,+0.0f

    // Prefetch row 0 of x (float4) and y (pre-packed f32x2 pairs).
    const float4* xrow = (const float4*)(xb + (size_t)(2 * i + r0) * W_);
    float4 xa = xrow[2 * lane];
    float4 xc = xrow[2 * lane + 1];
    const ulonglong2* yrow = (const ulonglong2*)(yb + (size_t)(TOLC + r0) * W_ + TOLC);
    ulonglong2 yA = yrow[2 * lane];       // pairs (y0,y1)
    ulonglong2 yB = yrow[2 * lane + 1];   // pairs (y2,y3)

#pragma unroll 1
    for (int rr = 0; rr < 8; rr++) {
        const unsigned boff = (rr & 1) ? (unsigned)(W_ * 4) : 0u;
        sts128(base + boff + s0, xa);
        sts128(base + boff + s1, xc);

        const uint64_t py0 = yA.x, py1 = yA.y, py2 = yB.x, py3 = yB.y;

        if (rr < 7) {   // prefetch next x AND y rows while this row computes
            const float4* xn = (const float4*)(xb + (size_t)(2 * i + r0 + rr + 1) * W_);
            xa = xn[2 * lane];
            xc = xn[2 * lane + 1];
            const ulonglong2* yn =
                (const ulonglong2*)(yb + (size_t)(TOLC + r0 + rr + 1) * W_ + TOLC);
            yA = yn[2 * lane];
            yB = yn[2 * lane + 1];
        }

        // Single per-row barrier: orders this row's STS before the LDS batch,
        // and (by bounding lane slip to <1 iteration) the next iteration's STS
        // to the OTHER buffer can never pass a lane still reading this one.
        __syncwarp();

        uint64_t wd[20];   // 40-float window x[8L .. 8L+40) as 20 f32x2 pairs
#pragma unroll
        for (int m = 0; m < 10; m++)
            lds_2b64(base + boff + roff[m], wd[2 * m], wd[2 * m + 1]);

#pragma unroll
        for (int j = 0; j < NS; j++) {
            uint64_t a0 = f2abs(f2fma(py0, NEG1_X2, wd[j + 0]));  // |x - y|
            uint64_t a1 = f2abs(f2fma(py1, NEG1_X2, wd[j + 1]));
            uint64_t a2 = f2abs(f2fma(py2, NEG1_X2, wd[j + 2]));
            uint64_t a3 = f2abs(f2fma(py3, NEG1_X2, wd[j + 3]));
            acc[j] = f2add(acc[j], f2add(f2add(a0, a1), f2add(a2, a3)));
        }
    }

    // Reduce: lane j keeps shift-column j's warp sum; idle lanes contribute 0.
    float keep = 0.0f;
#pragma unroll
    for (int j = 0; j < NS; j++) {
        float lo, hi; unpack2(acc[j], lo, hi);
        float v = (lane < 28) ? (lo + hi) : 0.0f;
#pragma unroll
        for (int off = 16; off; off >>= 1) v += __shfl_xor_sync(0xffffffffu, v, off);
        if (lane == j) keep = v;
    }
    if (lane < NS) atomicAdd(&g_acc[i * NS + lane], keep);
}

__global__ void final_kernel(float* __restrict__ out) {
    const int lane = threadIdx.x;   // 32 threads
    // Batched predicated loads: all 10 LDGs issue back-to-back (one round trip).
    float vals[10];
#pragma unroll
    for (int m = 0; m < 10; m++) {
        const int idx = lane + 32 * m;
        vals[m] = (idx < NS * NS) ? g_acc[idx] : 3.4e38f;
    }
    // Reset accumulators (restore launch invariant); independent of the loads.
#pragma unroll
    for (int m = 0; m < 10; m++) {
        const int idx = lane + 32 * m;
        if (idx < NS * NS) g_acc[idx] = 0.0f;
    }
    // Register tree-min, then warp shuffle-min.
#pragma unroll
    for (int s = 5; s > 0; s >>= 1)        // 10 -> 5 -> (handled below)
        ;
    float v = vals[0];
#pragma unroll
    for (int m = 1; m < 10; m++) v = fminf(v, vals[m]);
#pragma unroll
    for (int off = 16; off; off >>= 1)
        v = fminf(v, __shfl_xor_sync(0xffffffffu, v, off));
    if (lane == 0) out[0] = v * (1.0f / COUNT_F);
}

extern "C" void kernel_launch(void* const* d_in, const int* in_sizes, int n_in,
                              void* d_out, int out_size) {
    (void)in_sizes; (void)n_in; (void)out_size;
    const float* x = (const float*)d_in[0];
    const float* y = (const float*)d_in[1];
    float* out = (float*)d_out;

    dim3 grid(7, NS, 12);
    corr_kernel<<<grid, 128>>>(x, y);
    final_kernel<<<1, 32>>>(out);
}